// round 8
// baseline (speedup 1.0000x reference)
#include <cuda_runtime.h>
#include <cuda_bf16.h>
#include <cstdint>

#define BATCH 16
#define T0 64000
#define T1 32000
#define CH1 32
#define T2 16000
#define CH2 64
#define T3 8000
#define CH3 128
#define NH 64
#define NB 64
#define X2R 8072
#define NPB 63      // conv3 blocks per batch = pool partials

// ---------------- PTX helpers ----------------
__device__ __forceinline__ uint32_t smem_u32(const void* p) {
    uint32_t a;
    asm("{ .reg .u64 t; cvta.to.shared.u64 t, %1; cvt.u32.u64 %0, t; }" : "=r"(a) : "l"(p));
    return a;
}
#define MBAR_INIT(a, n) asm volatile("mbarrier.init.shared.b64 [%0], %1;" :: "r"(a), "r"((uint32_t)(n)) : "memory")
#define MBAR_EXPECT(a, tx) asm volatile("mbarrier.arrive.expect_tx.shared.b64 _, [%0], %1;" :: "r"(a), "r"((uint32_t)(tx)) : "memory")
#define MBAR_ARRIVE(a) asm volatile("mbarrier.arrive.shared.b64 _, [%0];" :: "r"(a) : "memory")
#define MBAR_WAIT(a, ph) do { \
    uint32_t _m = (a), _p = (ph), _d; \
    asm volatile("{ .reg .pred p; mbarrier.try_wait.parity.acquire.cta.shared::cta.b64 p, [%1], %2; selp.b32 %0, 1, 0, p; }" \
        : "=r"(_d) : "r"(_m), "r"(_p) : "memory"); \
    if (!_d) { \
        asm volatile("{ .reg .pred P1; WL_%=: mbarrier.try_wait.parity.acquire.cta.shared::cta.b64 P1, [%0], %1, 0x989680; @P1 bra.uni WD_%=; bra.uni WL_%=; WD_%=: }" \
            :: "r"(_m), "r"(_p) : "memory"); \
    } } while (0)
#define BULK_G2S(dst, src, bytes, mbar) \
    asm volatile("cp.async.bulk.shared::cluster.global.mbarrier::complete_tx::bytes [%0], [%1], %2, [%3];" \
        :: "r"(dst), "l"(src), "r"((uint32_t)(bytes)), "r"(mbar) : "memory")
#define CP16(dst, src) asm volatile("cp.async.cg.shared.global [%0], [%1], 16;" :: "r"(dst), "l"(src))
#define CP_COMMIT() asm volatile("cp.async.commit_group;" ::: "memory")
#define CP_WAIT0() asm volatile("cp.async.wait_group 0;" ::: "memory")

#define LDSM_X4(r, addr) \
    asm volatile("ldmatrix.sync.aligned.m8n8.x4.shared.b16 {%0,%1,%2,%3}, [%4];" \
        : "=r"((r)[0]), "=r"((r)[1]), "=r"((r)[2]), "=r"((r)[3]) : "r"(addr))
#define LDSM_X4_T(r, addr) \
    asm volatile("ldmatrix.sync.aligned.m8n8.x4.trans.shared.b16 {%0,%1,%2,%3}, [%4];" \
        : "=r"((r)[0]), "=r"((r)[1]), "=r"((r)[2]), "=r"((r)[3]) : "r"(addr))
#define MMA16816(d, a, b0, b1) \
    asm volatile("mma.sync.aligned.m16n8k16.row.col.f32.bf16.bf16.f32 " \
        "{%0,%1,%2,%3}, {%4,%5,%6,%7}, {%8,%9}, {%0,%1,%2,%3};" \
        : "+f"((d)[0]), "+f"((d)[1]), "+f"((d)[2]), "+f"((d)[3]) \
        : "r"((a)[0]), "r"((a)[1]), "r"((a)[2]), "r"((a)[3]), "r"(b0), "r"(b1))

// ---------------- scratch ----------------
__device__ __nv_bfloat16 g_x2e[(size_t)BATCH * X2R * CH2];
__device__ __nv_bfloat16 g_x2o[(size_t)BATCH * X2R * CH2];
__device__ __nv_bfloat16 g_w2s[18 * 32 * 72];
__device__ __nv_bfloat16 g_w3s[18 * 64 * 136];
__device__ float g_poolpart[BATCH * NPB * CH3];
__device__ float g_amps[BATCH * NH];
__device__ float g_nmag[BATCH * NB];

// ---------------- prep: bf16 hi/lo weight split ----------------
__global__ void prep_kernel(const float* __restrict__ w2, const float* __restrict__ w3) {
    int tid = blockIdx.x * blockDim.x + threadIdx.x;
    int stride = gridDim.x * blockDim.x;
    for (int i = tid; i < 18 * 32 * 64; i += stride) {
        int co = i & 63, ci = (i >> 6) & 31, tp = i >> 11;
        int k = tp >> 1, p = tp & 1;
        float w = w2[(co * CH1 + ci) * 9 + k];
        __nv_bfloat16 h = __float2bfloat16_rn(w);
        __nv_bfloat16 v = p ? __float2bfloat16_rn(w - __bfloat162float(h)) : h;
        g_w2s[(tp * 32 + ci) * 72 + co] = v;
    }
    for (int i = tid; i < 18 * 64 * 128; i += stride) {
        int co = i & 127, ci = (i >> 7) & 63, tp = i >> 13;
        int k = tp >> 1, p = tp & 1;
        float w = w3[(co * CH2 + ci) * 9 + k];
        __nv_bfloat16 h = __float2bfloat16_rn(w);
        __nv_bfloat16 v = p ? __float2bfloat16_rn(w - __bfloat162float(h)) : h;
        g_w3s[(tp * 64 + ci) * 136 + co] = v;
    }
}

// ---------------- conv2 (with fused conv1 prologue): t-tile 256 ----------------
// smem layout (bytes from base):
//   [0,8)        weight mbar
//   [16, 4240)   audio tile: 1056 floats
//   C2_SAE       A even rows: 260 x 80
//   C2_SAO       A odd  rows: 260 x 80
//   C2_SW        w2 split: 18*32*144
#define C2_SAUD 16
#define C2_SAE  4352
#define C2_SAO  (C2_SAE + 260 * 80)
#define C2_SW   (C2_SAO + 260 * 80)
#define C2_WBYTES (18 * 32 * 144)
#define C2_SMEM (C2_SW + C2_WBYTES)
__global__ __launch_bounds__(256) void conv2_mma(const float* __restrict__ audio,
                                                 const float* __restrict__ w1,
                                                 const float* __restrict__ b1,
                                                 const float* __restrict__ b2v) {
    extern __shared__ char smem[];
    uint32_t sb = smem_u32(smem);
    float* s_a = reinterpret_cast<float*>(smem + C2_SAUD);
    int tid = threadIdx.x;
    int b = blockIdx.y;
    int t0 = blockIdx.x * 256;
    uint32_t MB = sb;
    if (tid == 0) MBAR_INIT(MB, 1);
    __syncthreads();
    if (tid == 0) {
        MBAR_EXPECT(MB, C2_WBYTES);
        BULK_G2S(sb + C2_SW, (const char*)g_w2s, C2_WBYTES, MB);
    }
    // ---- load audio tile: s_a[j] = audio[4*t0 - 12 + j], j in [0,1048) ----
    {
        const float* ab = audio + (size_t)b * T0;
        int gbase = 4 * t0 - 12;
        for (int j = tid; j < 1048; j += 256) {
            int gi = gbase + j;
            s_a[j] = (gi >= 0 && gi < T0) ? ab[gi] : 0.0f;
        }
    }
    __syncthreads();
    // ---- fused conv1: t1[u] for u = 2*t0-4 .. 2*t0+515 -> bf16 A tiles ----
    {
        int ci = tid & 31;
        float w[9];
#pragma unroll
        for (int k = 0; k < 9; k++) w[k] = __ldg(w1 + ci * 9 + k);
        float bias = __ldg(b1 + ci);
        for (int ul = tid >> 5; ul < 520; ul += 8) {
            int u = 2 * t0 - 4 + ul;
            float acc = bias;
#pragma unroll
            for (int k = 0; k < 9; k++) acc = fmaf(w[k], s_a[2 * ul + k], acc);
            float v = (u >= 0 && u < T1) ? fmaxf(acc, 0.0f) : 0.0f;
            __nv_bfloat16 bv = __float2bfloat16_rn(v);
            if (ul & 1) {
                int i = (ul - 1) >> 1;
                *reinterpret_cast<__nv_bfloat16*>(smem + C2_SAO + i * 80 + ci * 2) = bv;
            } else {
                int i = ul >> 1;
                *reinterpret_cast<__nv_bfloat16*>(smem + C2_SAE + i * 80 + ci * 2) = bv;
            }
        }
    }
    MBAR_WAIT(MB, 0);
    __syncthreads();

    int lane = tid & 31, w = tid >> 5;
    int gid = lane >> 2, tig = lane & 3;
    float d[2][8][4];
#pragma unroll
    for (int i = 0; i < 2; i++)
#pragma unroll
        for (int j = 0; j < 8; j++)
#pragma unroll
            for (int q = 0; q < 4; q++) d[i][j][q] = 0.0f;

    for (int tp = 0; tp < 18; tp++) {
        int k = tp >> 1;
        int par = k & 1;
        int j0 = par ? ((k - 5) / 2 + 2) : ((k - 4) / 2 + 2);
        uint32_t abase = sb + (par ? C2_SAO : C2_SAE);
        uint32_t wtile = sb + C2_SW + tp * 4608;
        uint32_t bb[2][4][4];
#pragma unroll
        for (int ks = 0; ks < 2; ks++)
#pragma unroll
            for (int nb2 = 0; nb2 < 4; nb2++) {
                uint32_t addr = wtile + (ks * 16 + (lane & 15)) * 144 + (nb2 * 16 + (lane >> 4) * 8) * 2;
                LDSM_X4_T(bb[ks][nb2], addr);
            }
#pragma unroll
        for (int ms = 0; ms < 2; ms++) {
            int mrow = w * 32 + ms * 16 + j0;
            uint32_t a[2][4];
#pragma unroll
            for (int ks = 0; ks < 2; ks++) {
                uint32_t addr = abase + (mrow + (lane & 15)) * 80 + (ks * 16 + (lane >> 4) * 8) * 2;
                LDSM_X4(a[ks], addr);
            }
#pragma unroll
            for (int ks = 0; ks < 2; ks++)
#pragma unroll
                for (int nb2 = 0; nb2 < 4; nb2++) {
                    MMA16816(d[ms][nb2 * 2],     a[ks], bb[ks][nb2][0], bb[ks][nb2][1]);
                    MMA16816(d[ms][nb2 * 2 + 1], a[ks], bb[ks][nb2][2], bb[ks][nb2][3]);
                }
        }
    }
#pragma unroll
    for (int ms = 0; ms < 2; ms++)
#pragma unroll
        for (int nb = 0; nb < 8; nb++) {
            int co = nb * 8 + tig * 2;
            float2 bias = *reinterpret_cast<const float2*>(b2v + co);
#pragma unroll
            for (int half = 0; half < 2; half++) {
                int t = t0 + w * 32 + ms * 16 + gid + half * 8;
                if (t < T2) {
                    float v0 = fmaxf(d[ms][nb][half * 2]     + bias.x, 0.0f);
                    float v1 = fmaxf(d[ms][nb][half * 2 + 1] + bias.y, 0.0f);
                    __nv_bfloat162 pv;
                    pv.x = __float2bfloat16_rn(v0);
                    pv.y = __float2bfloat16_rn(v1);
                    size_t idx = ((size_t)b * X2R + (t >> 1) + 4) * CH2 + co;
                    if (t & 1) *reinterpret_cast<__nv_bfloat162*>(&g_x2o[idx]) = pv;
                    else       *reinterpret_cast<__nv_bfloat162*>(&g_x2e[idx]) = pv;
                }
            }
        }
}

// ---------------- conv3: HMMA 2Mx4N warps, fused mean-pool epilogue ----------------
#define C3_AROWS 132
#define C3_SAE 2048
#define C3_SAO (2048 + C3_AROWS * 144)
#define C3_SW  (2048 + 2 * C3_AROWS * 144)
#define C3_WSTG 17408
#define C3_SMEM (C3_SW + 4 * C3_WSTG)
__global__ __launch_bounds__(256) void conv3_mma(const float* __restrict__ b3v) {
    extern __shared__ char smem[];
    uint32_t sb = smem_u32(smem);
    float* spool = reinterpret_cast<float*>(smem + 1024);  // [2 wm][128 co]
    int tid = threadIdx.x;
    int b = blockIdx.y;
    int t0 = blockIdx.x * 128;
    if (tid == 0) {
        for (int s = 0; s < 4; s++) { MBAR_INIT(sb + 8 * s, 1); MBAR_INIT(sb + 32 + 8 * s, 256); }
    }
    __syncthreads();
    if (tid == 0) {
        for (int s = 0; s < 4; s++) {
            MBAR_EXPECT(sb + 8 * s, C3_WSTG);
            BULK_G2S(sb + C3_SW + s * C3_WSTG, (const char*)g_w3s + s * (size_t)C3_WSTG, C3_WSTG, sb + 8 * s);
        }
    }
    for (int c = tid; c < C3_AROWS * 8; c += 256) {
        int row = c >> 3, part = c & 7;
        size_t so = (((size_t)b * X2R + t0 + 2 + row) * 64 + part * 8) * 2;
        CP16(sb + C3_SAE + row * 144 + part * 16, (const char*)g_x2e + so);
        CP16(sb + C3_SAO + row * 144 + part * 16, (const char*)g_x2o + so);
    }
    CP_COMMIT();
    CP_WAIT0();
    __syncthreads();

    int lane = tid & 31, w = tid >> 5;
    int wm = w >> 2, wn = w & 3;
    int gid = lane >> 2, tig = lane & 3;
    float d[4][4][4];
#pragma unroll
    for (int i = 0; i < 4; i++)
#pragma unroll
        for (int j = 0; j < 4; j++)
#pragma unroll
            for (int q = 0; q < 4; q++) d[i][j][q] = 0.0f;

    for (int tp = 0; tp < 18; tp++) {
        int s = tp & 3;
        MBAR_WAIT(sb + 8 * s, (tp >> 2) & 1);
        int k = tp >> 1;
        int par = k & 1;
        int j0 = par ? ((k - 5) / 2 + 2) : ((k - 4) / 2 + 2);
        uint32_t abase = sb + (par ? C3_SAO : C3_SAE);
        uint32_t wtile = sb + C3_SW + s * C3_WSTG;
        uint32_t bb[2][4][4];
#pragma unroll
        for (int nbl = 0; nbl < 2; nbl++)
#pragma unroll
            for (int ks = 0; ks < 4; ks++) {
                uint32_t addr = wtile + (ks * 16 + (lane & 15)) * 272
                              + (wn * 32 + nbl * 16 + (lane >> 4) * 8) * 2;
                LDSM_X4_T(bb[nbl][ks], addr);
            }
#pragma unroll
        for (int ms = 0; ms < 4; ms++) {
            int mrow = wm * 64 + ms * 16 + j0;
            uint32_t a[4][4];
#pragma unroll
            for (int ks = 0; ks < 4; ks++) {
                uint32_t addr = abase + (mrow + (lane & 15)) * 144 + (ks * 16 + (lane >> 4) * 8) * 2;
                LDSM_X4(a[ks], addr);
            }
#pragma unroll
            for (int nbl = 0; nbl < 2; nbl++)
#pragma unroll
                for (int ks = 0; ks < 4; ks++) {
                    MMA16816(d[ms][nbl * 2],     a[ks], bb[nbl][ks][0], bb[nbl][ks][1]);
                    MMA16816(d[ms][nbl * 2 + 1], a[ks], bb[nbl][ks][2], bb[nbl][ks][3]);
                }
        }
        MBAR_ARRIVE(sb + 32 + 8 * s);
        if (tid == 0 && tp + 4 < 18) {
            MBAR_WAIT(sb + 32 + 8 * s, (tp >> 2) & 1);
            MBAR_EXPECT(sb + 8 * s, C3_WSTG);
            BULK_G2S(sb + C3_SW + s * C3_WSTG, (const char*)g_w3s + (tp + 4) * (size_t)C3_WSTG, C3_WSTG, sb + 8 * s);
        }
    }

    float psx[4], psy[4];
#pragma unroll
    for (int nb = 0; nb < 4; nb++) {
        int co = wn * 32 + nb * 8 + tig * 2;
        float2 bias = *reinterpret_cast<const float2*>(b3v + co);
        float sx = 0.0f, sy = 0.0f;
#pragma unroll
        for (int ms = 0; ms < 4; ms++)
#pragma unroll
            for (int half = 0; half < 2; half++) {
                int t = t0 + wm * 64 + ms * 16 + gid + half * 8;
                if (t < T3) {
                    sx += fmaxf(d[ms][nb][half * 2]     + bias.x, 0.0f);
                    sy += fmaxf(d[ms][nb][half * 2 + 1] + bias.y, 0.0f);
                }
            }
        psx[nb] = sx; psy[nb] = sy;
    }
#pragma unroll
    for (int off = 4; off < 32; off <<= 1)
#pragma unroll
        for (int nb = 0; nb < 4; nb++) {
            psx[nb] += __shfl_xor_sync(0xffffffffu, psx[nb], off);
            psy[nb] += __shfl_xor_sync(0xffffffffu, psy[nb], off);
        }
    if (lane < 4) {
#pragma unroll
        for (int nb = 0; nb < 4; nb++) {
            int co = wn * 32 + nb * 8 + lane * 2;
            spool[wm * 128 + co]     = psx[nb];
            spool[wm * 128 + co + 1] = psy[nb];
        }
    }
    __syncthreads();
    if (tid < 128)
        g_poolpart[(b * NPB + blockIdx.x) * CH3 + tid] = spool[tid] + spool[128 + tid];
}

// ---------------- head ----------------
__global__ void head_kernel(const float* __restrict__ wl, const float* __restrict__ bl) {
    __shared__ float sp[128];
    __shared__ float s_amp[64];
    __shared__ float s_sum;
    int b = blockIdx.x, j = threadIdx.x;
    float s = 0.0f;
    for (int p = 0; p < NPB; p++) s += g_poolpart[(b * NPB + p) * CH3 + j];
    sp[j] = s * (1.0f / 8000.0f);
    __syncthreads();
    float dot = __ldg(bl + j);
    for (int c = 0; c < 128; c++) dot = fmaf(sp[c], __ldg(wl + j * 128 + c), dot);
    if (j < 64) s_amp[j] = fmaxf(dot, 0.0f);
    __syncthreads();
    if (j == 0) {
        float t = 0.0f;
        for (int h = 0; h < 64; h++) t += s_amp[h];
        s_sum = t + 1e-6f;
    }
    __syncthreads();
    if (j < 64) g_amps[b * 64 + j] = s_amp[j] / s_sum;
    else        g_nmag[b * 64 + (j - 64)] = dot;
}

// ---------------- synth ----------------
__global__ __launch_bounds__(256) void synth_kernel(const float* __restrict__ f0,
                                                    const float* __restrict__ wn,
                                                    float* __restrict__ out) {
    __shared__ float s_amps[64];
    __shared__ float s_nm[64];
    int b = blockIdx.y;
    if (threadIdx.x < 64)       s_amps[threadIdx.x]    = g_amps[b * 64 + threadIdx.x];
    else if (threadIdx.x < 128) s_nm[threadIdx.x - 64] = g_nmag[b * 64 + threadIdx.x - 64];
    __syncthreads();
    int t = blockIdx.x * 256 + threadIdx.x;

    constexpr float DELTA  = 4.0f / 63999.0f;
    constexpr float TWO_PI = 6.283185307179586f;
    float tf  = (float)t * DELTA;
    float a   = TWO_PI * f0[(size_t)b * T0 + t];

    constexpr double PIO2_D = 1.5707963267948966192313216916397514;
    constexpr float RC1 = (float)PIO2_D;
    constexpr float RC2 = (float)(PIO2_D - (double)RC1);
    constexpr float INV_PIO2 = 0.63661977236758134308f;
    const float MAGIC = 12582912.0f;

    float acc = 0.0f;
#pragma unroll
    for (int h = 1; h <= 64; h++) {
        float bh = a * (float)h;
        float x  = bh * tf;
        float kr = fmaf(x, INV_PIO2, MAGIC);
        unsigned q = (unsigned)__float_as_int(kr);
        float kf = kr - MAGIC;
        float r = fmaf(kf, -RC1, x);
        r = fmaf(kf, -RC2, r);
        float z = r * r;
        float ps = fmaf(-1.9515295891e-4f, z, 8.3321608736e-3f);
        ps = fmaf(ps, z, -1.6666654611e-1f);
        ps = ps * z;
        float sres = fmaf(ps, r, r);
        float pc = fmaf(2.443315711809948e-5f, z, -1.388731625493765e-3f);
        pc = fmaf(pc, z, 4.166664568298827e-2f);
        pc = fmaf(pc, z, -0.5f);
        float cres = fmaf(pc, z, 1.0f);
        float v = (q & 1u) ? cres : sres;
        v = __int_as_float(__float_as_int(v) ^ (int)((q << 30) & 0x80000000u));
        acc = fmaf(s_amps[h - 1], v, acc);
    }
    int bin = t / 1000;
    float shaped = wn[(size_t)b * T0 + t] * s_nm[bin];
    out[(size_t)b * T0 + t] = acc + shaped;
}

extern "C" void kernel_launch(void* const* d_in, const int* in_sizes, int n_in,
                              void* d_out, int out_size) {
    (void)in_sizes; (void)n_in; (void)out_size;
    const float* audio = (const float*)d_in[0];
    const float* f0    = (const float*)d_in[1];
    const float* wn    = (const float*)d_in[2];
    const float* w1    = (const float*)d_in[3];
    const float* b1    = (const float*)d_in[4];
    const float* w2    = (const float*)d_in[5];
    const float* b2    = (const float*)d_in[6];
    const float* w3    = (const float*)d_in[7];
    const float* b3    = (const float*)d_in[8];
    const float* wl    = (const float*)d_in[9];
    const float* bl    = (const float*)d_in[10];
    float* out = (float*)d_out;

    cudaFuncSetAttribute(conv2_mma, cudaFuncAttributeMaxDynamicSharedMemorySize, C2_SMEM);
    cudaFuncSetAttribute(conv3_mma, cudaFuncAttributeMaxDynamicSharedMemorySize, C3_SMEM);

    prep_kernel<<<64, 256>>>(w2, w3);
    conv2_mma<<<dim3(63, 16), 256, C2_SMEM>>>(audio, w1, b1, b2);
    conv3_mma<<<dim3(63, 16), 256, C3_SMEM>>>(b3);
    head_kernel<<<16, 128>>>(wl, bl);
    synth_kernel<<<dim3(250, 16), 256>>>(f0, wn, out);
}